// round 1
// baseline (speedup 1.0000x reference)
#include <cuda_runtime.h>

// ---------------- problem constants ----------------
constexpr int B_    = 4;
constexpr int S_    = 2048;
constexpr int D_    = 1024;     // model dim == H*DK
constexpr int C_    = 32;       // chunks
constexpr int NL_   = 256;      // N*L keys per chunk
constexpr int H_    = 16;
constexpr int DK_   = 64;
constexpr int CHK_  = 64;       // CHUNK
constexpr int VALID = S_ - (CHK_ - 1);   // 1985 valid shifted rows
constexpr int MQ    = B_ * C_ * CHK_;    // 8192  (hb/q/attn-out rows)
constexpr int MKV   = B_ * C_ * NL_;     // 32768 (e rows)
constexpr float SCALE = 0.125f;          // 1/sqrt(64)
constexpr float EPS_  = 1e-5f;

// ---------------- scratch (allocation-free: __device__ globals) ----------------
__device__ float g_hb[(size_t)MQ  * D_];   // normalized+shifted h blocks
__device__ float g_q [(size_t)MQ  * D_];
__device__ float g_k [(size_t)MKV * D_];
__device__ float g_v [(size_t)MKV * D_];
__device__ float g_ao[(size_t)MQ  * D_];   // attention output (pre O-proj)

// ---------------- 1) LayerNorm + shift ----------------
// hb[row] = LN(h[b, j+63]) for j<VALID else 0,  row = b*2048 + j
__global__ void __launch_bounds__(256) ln_kernel(const float* __restrict__ h,
                                                 const float* __restrict__ gamma,
                                                 const float* __restrict__ beta) {
    int row = blockIdx.x;
    int b = row >> 11, j = row & 2047;
    float* dst = g_hb + (size_t)row * D_;
    int t = threadIdx.x;
    if (j >= VALID) {
        for (int i = t; i < D_; i += 256) dst[i] = 0.f;
        return;
    }
    const float* src = h + ((size_t)b * S_ + (j + CHK_ - 1)) * D_;
    float x[4];
    float s = 0.f, ss = 0.f;
    #pragma unroll
    for (int r = 0; r < 4; r++) {
        float v = src[t + r * 256];
        x[r] = v; s += v; ss += v * v;
    }
    #pragma unroll
    for (int o = 16; o; o >>= 1) {
        s  += __shfl_down_sync(0xffffffffu, s,  o);
        ss += __shfl_down_sync(0xffffffffu, ss, o);
    }
    __shared__ float rs[8], rss[8];
    int w = t >> 5, l = t & 31;
    if (l == 0) { rs[w] = s; rss[w] = ss; }
    __syncthreads();
    float S1 = 0.f, S2 = 0.f;
    #pragma unroll
    for (int i = 0; i < 8; i++) { S1 += rs[i]; S2 += rss[i]; }
    float mu  = S1 * (1.f / D_);
    float var = S2 * (1.f / D_) - mu * mu;
    float inv = rsqrtf(var + EPS_);
    #pragma unroll
    for (int r = 0; r < 4; r++) {
        int c = t + r * 256;
        dst[c] = (x[r] - mu) * inv * gamma[c] + beta[c];
    }
}

// ---------------- 2) generic fp32 GEMM: C = A(Mx1024) * W(1024x1024) + bias ----------------
// 128x128 tile, BK=16, 256 threads, 8x8 per thread
__global__ void __launch_bounds__(256) gemm_bias(const float* __restrict__ A,
                                                 const float* __restrict__ W,
                                                 const float* __restrict__ bias,
                                                 float* __restrict__ Cmat) {
    __shared__ float As[16][128];
    __shared__ float Bs[16][128];
    int bm = blockIdx.y * 128;
    int bn = blockIdx.x * 128;
    int t  = threadIdx.x;
    int tx = t & 15, ty = t >> 4;
    float acc[8][8] = {};
    int am = t >> 2, ag = (t & 3) * 4;         // A-load: row am/am+64, k-group ag
    int bk = t >> 5, bnn = (t & 31) * 4;       // B-load: k-row bk/bk+8, 4 cols

    for (int k0 = 0; k0 < 1024; k0 += 16) {
        #pragma unroll
        for (int r = 0; r < 2; r++) {
            int m = am + r * 64;
            float4 v = *(const float4*)(A + (size_t)(bm + m) * 1024 + k0 + ag);
            As[ag + 0][m] = v.x; As[ag + 1][m] = v.y;
            As[ag + 2][m] = v.z; As[ag + 3][m] = v.w;
        }
        #pragma unroll
        for (int r = 0; r < 2; r++) {
            int kk = bk + r * 8;
            *(float4*)&Bs[kk][bnn] = *(const float4*)(W + (size_t)(k0 + kk) * 1024 + bn + bnn);
        }
        __syncthreads();
        #pragma unroll
        for (int kk = 0; kk < 16; kk++) {
            float4 a0 = *(const float4*)&As[kk][ty * 8];
            float4 a1 = *(const float4*)&As[kk][ty * 8 + 4];
            float4 b0 = *(const float4*)&Bs[kk][tx * 8];
            float4 b1 = *(const float4*)&Bs[kk][tx * 8 + 4];
            float a[8] = {a0.x, a0.y, a0.z, a0.w, a1.x, a1.y, a1.z, a1.w};
            float b[8] = {b0.x, b0.y, b0.z, b0.w, b1.x, b1.y, b1.z, b1.w};
            #pragma unroll
            for (int i = 0; i < 8; i++)
                #pragma unroll
                for (int j = 0; j < 8; j++)
                    acc[i][j] += a[i] * b[j];
        }
        __syncthreads();
    }
    #pragma unroll
    for (int i = 0; i < 8; i++) {
        int m = bm + ty * 8 + i;
        #pragma unroll
        for (int j = 0; j < 8; j += 4) {
            int n = bn + tx * 8 + j;
            float4 v;
            v.x = acc[i][j + 0] + bias[n + 0];
            v.y = acc[i][j + 1] + bias[n + 1];
            v.z = acc[i][j + 2] + bias[n + 2];
            v.w = acc[i][j + 3] + bias[n + 3];
            *(float4*)(Cmat + (size_t)m * 1024 + n) = v;
        }
    }
}

// ---------------- 3) attention per (b,c,h) ----------------
// q: 64x64, k/v: 256x64; scores 64x256 softmax; out 64x64
__global__ void __launch_bounds__(256) attn_kernel() {
    extern __shared__ float sm[];
    float* qs = sm;                    // 64 x 68
    float* ks = sm + 64 * 68;          // 64 x 68 (k, then reused for v)
    float* sc = sm + 2 * 64 * 68;      // 64 x 256
    int blk = blockIdx.x;              // b*512 + c*16 + h
    int hh  = blk & 15;
    int bc  = blk >> 4;
    const float* qp = g_q + (size_t)bc * 64 * 1024 + hh * 64;
    const float* kp = g_k + (size_t)bc * 256 * 1024 + hh * 64;
    const float* vp = g_v + (size_t)bc * 256 * 1024 + hh * 64;
    int t = threadIdx.x;

    #pragma unroll
    for (int r = 0; r < 16; r++) {
        int idx = t + r * 256;
        int i = idx >> 6, d = idx & 63;
        qs[i * 68 + d] = qp[(size_t)i * 1024 + d];
    }

    // scores
    for (int jt = 0; jt < 4; jt++) {
        __syncthreads();
        #pragma unroll
        for (int r = 0; r < 16; r++) {
            int idx = t + r * 256;
            int j = idx >> 6, d = idx & 63;
            ks[j * 68 + d] = kp[(size_t)(jt * 64 + j) * 1024 + d];
        }
        __syncthreads();
        #pragma unroll
        for (int r = 0; r < 16; r++) {
            int idx = t + r * 256;
            int i = idx >> 6, j = idx & 63;
            float s = 0.f;
            #pragma unroll
            for (int kk = 0; kk < 16; kk++) {
                float4 qa = *(const float4*)&qs[i * 68 + kk * 4];
                float4 kb = *(const float4*)&ks[j * 68 + kk * 4];
                s += qa.x * kb.x + qa.y * kb.y + qa.z * kb.z + qa.w * kb.w;
            }
            sc[i * 256 + jt * 64 + j] = s * SCALE;
        }
    }
    __syncthreads();

    // softmax: warp w owns rows w*8..w*8+7
    {
        int w = t >> 5, l = t & 31;
        for (int rr = 0; rr < 8; rr++) {
            float* row = sc + (w * 8 + rr) * 256;
            float m = -1e30f;
            float ev[8];
            #pragma unroll
            for (int c = 0; c < 8; c++) m = fmaxf(m, row[l + c * 32]);
            #pragma unroll
            for (int o = 16; o; o >>= 1) m = fmaxf(m, __shfl_xor_sync(0xffffffffu, m, o));
            float sum = 0.f;
            #pragma unroll
            for (int c = 0; c < 8; c++) { ev[c] = expf(row[l + c * 32] - m); sum += ev[c]; }
            #pragma unroll
            for (int o = 16; o; o >>= 1) sum += __shfl_xor_sync(0xffffffffu, sum, o);
            float inv = 1.f / sum;
            #pragma unroll
            for (int c = 0; c < 8; c++) row[l + c * 32] = ev[c] * inv;
        }
    }

    // out = P @ V : thread (ty,tx) computes 4x4 tile
    float acc[4][4] = {};
    int tx = t & 15, ty = t >> 4;
    for (int jt = 0; jt < 4; jt++) {
        __syncthreads();
        #pragma unroll
        for (int r = 0; r < 16; r++) {
            int idx = t + r * 256;
            int j = idx >> 6, d = idx & 63;
            ks[j * 68 + d] = vp[(size_t)(jt * 64 + j) * 1024 + d];
        }
        __syncthreads();
        #pragma unroll 4
        for (int jj = 0; jj < 64; jj++) {
            float4 vv = *(const float4*)&ks[jj * 68 + tx * 4];
            float p[4];
            #pragma unroll
            for (int ii = 0; ii < 4; ii++) p[ii] = sc[(ty * 4 + ii) * 256 + jt * 64 + jj];
            #pragma unroll
            for (int ii = 0; ii < 4; ii++) {
                acc[ii][0] += p[ii] * vv.x;
                acc[ii][1] += p[ii] * vv.y;
                acc[ii][2] += p[ii] * vv.z;
                acc[ii][3] += p[ii] * vv.w;
            }
        }
    }
    float* op = g_ao + (size_t)bc * 64 * 1024 + hh * 64;
    #pragma unroll
    for (int ii = 0; ii < 4; ii++) {
        float4 v4 = make_float4(acc[ii][0], acc[ii][1], acc[ii][2], acc[ii][3]);
        *(float4*)(op + (size_t)(ty * 4 + ii) * 1024 + tx * 4) = v4;
    }
}

// ---------------- 4) O-projection + shift + residual ----------------
__global__ void __launch_bounds__(256) gemm_final(const float* __restrict__ A,
                                                  const float* __restrict__ W,
                                                  const float* __restrict__ bias,
                                                  const float* __restrict__ resid,
                                                  float* __restrict__ out) {
    __shared__ float As[16][128];
    __shared__ float Bs[16][128];
    int bm = blockIdx.y * 128;
    int bn = blockIdx.x * 128;
    int t  = threadIdx.x;
    int tx = t & 15, ty = t >> 4;
    float acc[8][8] = {};
    int am = t >> 2, ag = (t & 3) * 4;
    int bk = t >> 5, bnn = (t & 31) * 4;

    for (int k0 = 0; k0 < 1024; k0 += 16) {
        #pragma unroll
        for (int r = 0; r < 2; r++) {
            int m = am + r * 64;
            float4 v = *(const float4*)(A + (size_t)(bm + m) * 1024 + k0 + ag);
            As[ag + 0][m] = v.x; As[ag + 1][m] = v.y;
            As[ag + 2][m] = v.z; As[ag + 3][m] = v.w;
        }
        #pragma unroll
        for (int r = 0; r < 2; r++) {
            int kk = bk + r * 8;
            *(float4*)&Bs[kk][bnn] = *(const float4*)(W + (size_t)(k0 + kk) * 1024 + bn + bnn);
        }
        __syncthreads();
        #pragma unroll
        for (int kk = 0; kk < 16; kk++) {
            float4 a0 = *(const float4*)&As[kk][ty * 8];
            float4 a1 = *(const float4*)&As[kk][ty * 8 + 4];
            float4 b0 = *(const float4*)&Bs[kk][tx * 8];
            float4 b1 = *(const float4*)&Bs[kk][tx * 8 + 4];
            float a[8] = {a0.x, a0.y, a0.z, a0.w, a1.x, a1.y, a1.z, a1.w};
            float b[8] = {b0.x, b0.y, b0.z, b0.w, b1.x, b1.y, b1.z, b1.w};
            #pragma unroll
            for (int i = 0; i < 8; i++)
                #pragma unroll
                for (int j = 0; j < 8; j++)
                    acc[i][j] += a[i] * b[j];
        }
        __syncthreads();
    }
    #pragma unroll
    for (int i = 0; i < 8; i++) {
        int m = bm + ty * 8 + i;           // global proj row
        int b = m >> 11, j = m & 2047;
        if (j >= VALID) continue;          // dropped by the reference's truncation
        size_t orow = ((size_t)b * S_ + j + (CHK_ - 1)) * 1024;
        #pragma unroll
        for (int jc = 0; jc < 8; jc += 4) {
            int n = bn + tx * 8 + jc;
            float4 rr = *(const float4*)(resid + orow + n);
            float4 v;
            v.x = acc[i][jc + 0] + bias[n + 0] + rr.x;
            v.y = acc[i][jc + 1] + bias[n + 1] + rr.y;
            v.z = acc[i][jc + 2] + bias[n + 2] + rr.z;
            v.w = acc[i][jc + 3] + bias[n + 3] + rr.w;
            *(float4*)(out + orow + n) = v;
        }
    }
}

// ---------------- 5) rows 0..62: pure residual ----------------
__global__ void __launch_bounds__(256) head_copy(const float* __restrict__ h,
                                                 float* __restrict__ out) {
    int idx = blockIdx.x * 256 + threadIdx.x;   // over B*63*1024
    int d = idx & 1023;
    int r = idx >> 10;                          // b*63 + t
    int b = r / 63, tt = r % 63;
    size_t off = ((size_t)b * S_ + tt) * 1024 + d;
    out[off] = h[off];
}

// ---------------- launch ----------------
extern "C" void kernel_launch(void* const* d_in, const int* in_sizes, int n_in,
                              void* d_out, int out_size) {
    const float* h     = (const float*)d_in[0];
    const float* e     = (const float*)d_in[1];
    const float* Wq    = (const float*)d_in[2];
    const float* bq    = (const float*)d_in[3];
    const float* Wk    = (const float*)d_in[4];
    const float* bk    = (const float*)d_in[5];
    const float* Wv    = (const float*)d_in[6];
    const float* bv    = (const float*)d_in[7];
    const float* Wo    = (const float*)d_in[8];
    const float* bo    = (const float*)d_in[9];
    const float* gamma = (const float*)d_in[10];
    const float* beta  = (const float*)d_in[11];
    float* out = (float*)d_out;

    float *hb, *q, *k, *v, *ao;
    cudaGetSymbolAddress((void**)&hb, g_hb);
    cudaGetSymbolAddress((void**)&q,  g_q);
    cudaGetSymbolAddress((void**)&k,  g_k);
    cudaGetSymbolAddress((void**)&v,  g_v);
    cudaGetSymbolAddress((void**)&ao, g_ao);

    ln_kernel<<<MQ, 256>>>(h, gamma, beta);
    gemm_bias<<<dim3(8, MQ  / 128), 256>>>(hb, Wq, bq, q);
    gemm_bias<<<dim3(8, MKV / 128), 256>>>(e,  Wk, bk, k);
    gemm_bias<<<dim3(8, MKV / 128), 256>>>(e,  Wv, bv, v);

    int attn_smem = (2 * 64 * 68 + 64 * 256) * (int)sizeof(float);  // 100352 B
    cudaFuncSetAttribute(attn_kernel, cudaFuncAttributeMaxDynamicSharedMemorySize, attn_smem);
    attn_kernel<<<B_ * C_ * H_, 256, attn_smem>>>();

    gemm_final<<<dim3(8, MQ / 128), 256>>>(ao, Wo, bo, h, out);
    head_copy<<<(B_ * 63 * 1024) / 256, 256>>>(h, out);
}

// round 4
// speedup vs baseline: 2.2250x; 2.2250x over previous
#include <cuda_runtime.h>
#include <cstdint>

// ---------------- problem constants ----------------
constexpr int B_    = 4;
constexpr int S_    = 2048;
constexpr int D_    = 1024;
constexpr int C_    = 32;
constexpr int H_    = 16;
constexpr int CHK_  = 64;
constexpr int VALID = S_ - (CHK_ - 1);   // 1985
constexpr int MQ    = B_ * C_ * CHK_;    // 8192
constexpr int MKV   = B_ * C_ * 256;     // 32768
constexpr float SCALE = 0.125f;
constexpr float EPS_  = 1e-5f;

// ---------------- scratch ----------------
__device__ float g_hb[(size_t)MQ  * D_];
__device__ float g_q [(size_t)MQ  * D_];
__device__ float g_k [(size_t)MKV * D_];
__device__ float g_v [(size_t)MKV * D_];
__device__ float g_ao[(size_t)MQ  * D_];

// ---------------- PTX helpers (plain compute_100 features only) ----------------
__device__ __forceinline__ uint32_t smem_u32(const void* p) {
    uint32_t a;
    asm("{ .reg .u64 t; cvta.to.shared.u64 t, %1; cvt.u32.u64 %0, t; }" : "=r"(a) : "l"(p));
    return a;
}
__device__ __forceinline__ void cp16(uint32_t dst, const void* src) {
    asm volatile("cp.async.cg.shared.global [%0], [%1], 16;" :: "r"(dst), "l"(src) : "memory");
}
#define CP_COMMIT() asm volatile("cp.async.commit_group;" ::: "memory")

__device__ __forceinline__ uint32_t f2tf(float x) {
    uint32_t r;
    asm("cvt.rna.tf32.f32 %0, %1;" : "=r"(r) : "f"(x));
    return r;
}
__device__ __forceinline__ void mma8(float* d, const uint32_t* a, const uint32_t* b) {
    asm volatile("mma.sync.aligned.m16n8k8.row.col.f32.tf32.tf32.f32 "
        "{%0,%1,%2,%3}, {%4,%5,%6,%7}, {%8,%9}, {%0,%1,%2,%3};"
        : "+f"(d[0]), "+f"(d[1]), "+f"(d[2]), "+f"(d[3])
        : "r"(a[0]), "r"(a[1]), "r"(a[2]), "r"(a[3]), "r"(b[0]), "r"(b[1]));
}

// ---------------- 1) LayerNorm + shift ----------------
__global__ void __launch_bounds__(256) ln_kernel(const float* __restrict__ h,
                                                 const float* __restrict__ gamma,
                                                 const float* __restrict__ beta) {
    int row = blockIdx.x;
    int b = row >> 11, j = row & 2047;
    float* dst = g_hb + (size_t)row * D_;
    int t = threadIdx.x;
    if (j >= VALID) {
        for (int i = t; i < D_; i += 256) dst[i] = 0.f;
        return;
    }
    const float* src = h + ((size_t)b * S_ + (j + CHK_ - 1)) * D_;
    float x[4];
    float s = 0.f, ss = 0.f;
    #pragma unroll
    for (int r = 0; r < 4; r++) {
        float v = src[t + r * 256];
        x[r] = v; s += v; ss += v * v;
    }
    #pragma unroll
    for (int o = 16; o; o >>= 1) {
        s  += __shfl_down_sync(0xffffffffu, s,  o);
        ss += __shfl_down_sync(0xffffffffu, ss, o);
    }
    __shared__ float rs[8], rss[8];
    int w = t >> 5, l = t & 31;
    if (l == 0) { rs[w] = s; rss[w] = ss; }
    __syncthreads();
    float S1 = 0.f, S2 = 0.f;
    #pragma unroll
    for (int i = 0; i < 8; i++) { S1 += rs[i]; S2 += rss[i]; }
    float mu  = S1 * (1.f / D_);
    float var = S2 * (1.f / D_) - mu * mu;
    float inv = rsqrtf(var + EPS_);
    #pragma unroll
    for (int r = 0; r < 4; r++) {
        int c = t + r * 256;
        dst[c] = (x[r] - mu) * inv * gamma[c] + beta[c];
    }
}

// ================= 2) tf32 mma.sync GEMM =================
// C(Mx1024) = A(Mx1024) * W(1024x1024) + bias [+ shift/residual if FINAL]
// CTA tile 128x128, BK=32, 4 warps (64x64 each), 3-stage cp.async pipeline.
// A_s[m][36] (pad->conflict-free frag loads), B_s[k][132].
constexpr int AS_STRIDE = 36;    // words
constexpr int BS_STRIDE = 132;   // words
constexpr int A_STAGE_W = 128 * AS_STRIDE;        // 4608 words
constexpr int B_STAGE_W = 32 * BS_STRIDE;         // 4224 words
constexpr int STAGE_W   = A_STAGE_W + B_STAGE_W;  // 8832 words
constexpr int GEMM_SMEM = 3 * STAGE_W * 4;        // 105984 bytes

template <bool FINAL>
__global__ void __launch_bounds__(128) gemm_tc(const float* __restrict__ A,
                                               const float* __restrict__ W,
                                               const float* __restrict__ bias,
                                               const float* __restrict__ resid,
                                               float* __restrict__ out) {
    extern __shared__ float sm[];
    const uint32_t smb = smem_u32(sm);

    const int t    = threadIdx.x;
    const int lane = t & 31;
    const int w    = t >> 5;
    const int wm   = (w >> 1) * 64;      // warp m offset in tile
    const int wn   = (w & 1) * 64;       // warp n offset in tile
    const int r    = lane >> 2;          // 0..7
    const int c    = lane & 3;           // 0..3

    const size_t bm = (size_t)blockIdx.y * 128;
    const size_t bn = (size_t)blockIdx.x * 128;

    // loader indices
    const int arow = t >> 3;             // 0..15 (+16p)
    const int ac8  = t & 7;              // float4 col group in k (0..7)
    const int bkk  = t >> 2;             // 0..31
    const int bc4  = t & 3;              // base n float4 group (i*4 + bc4)

    const float* Ag = A + (bm + arow) * 1024 + ac8 * 4;
    const float* Wg = W + (size_t)bkk * 1024 + bn + bc4 * 4;

    auto load_stage = [&](int s, int buf) {
        uint32_t abase = smb + (uint32_t)buf * STAGE_W * 4;
        uint32_t bbase = abase + A_STAGE_W * 4;
        const float* Asrc = Ag + s * 32;
        #pragma unroll
        for (int p = 0; p < 8; p++) {
            int row = arow + p * 16;
            cp16(abase + (uint32_t)(row * AS_STRIDE + ac8 * 4) * 4, Asrc + (size_t)p * 16 * 1024);
        }
        const float* Bsrc = Wg + (size_t)s * 32 * 1024;
        #pragma unroll
        for (int i = 0; i < 8; i++) {
            int n4 = bc4 + i * 4;
            // smem col group n4; global col offset beyond Wg is i*16 floats
            cp16(bbase + (uint32_t)(bkk * BS_STRIDE + n4 * 4) * 4, Bsrc + (size_t)i * 16);
        }
    };

    float acc[4][8][4];
    #pragma unroll
    for (int i = 0; i < 4; i++)
        #pragma unroll
        for (int j = 0; j < 8; j++)
            #pragma unroll
            for (int q = 0; q < 4; q++) acc[i][j][q] = 0.f;

    load_stage(0, 0); CP_COMMIT();
    load_stage(1, 1); CP_COMMIT();

    for (int s = 0; s < 32; s++) {
        if (s >= 30) { asm volatile("cp.async.wait_group 0;" ::: "memory"); }
        else         { asm volatile("cp.async.wait_group 1;" ::: "memory"); }
        __syncthreads();
        if (s + 2 < 32) { load_stage(s + 2, (s + 2) % 3); CP_COMMIT(); }

        const float* As = sm + (s % 3) * STAGE_W;
        const float* Bs = As + A_STAGE_W;
        #pragma unroll
        for (int ks = 0; ks < 4; ks++) {
            const int k8 = ks * 8;
            uint32_t a[4][4], b[8][2];
            #pragma unroll
            for (int mf = 0; mf < 4; mf++) {
                int m0 = wm + mf * 16 + r;
                a[mf][0] = f2tf(As[m0 * AS_STRIDE + k8 + c]);
                a[mf][1] = f2tf(As[(m0 + 8) * AS_STRIDE + k8 + c]);
                a[mf][2] = f2tf(As[m0 * AS_STRIDE + k8 + c + 4]);
                a[mf][3] = f2tf(As[(m0 + 8) * AS_STRIDE + k8 + c + 4]);
            }
            #pragma unroll
            for (int nf = 0; nf < 8; nf++) {
                int n0 = wn + nf * 8 + r;
                b[nf][0] = f2tf(Bs[(k8 + c) * BS_STRIDE + n0]);
                b[nf][1] = f2tf(Bs[(k8 + c + 4) * BS_STRIDE + n0]);
            }
            #pragma unroll
            for (int mf = 0; mf < 4; mf++)
                #pragma unroll
                for (int nf = 0; nf < 8; nf++)
                    mma8(acc[mf][nf], a[mf], b[nf]);
        }
        __syncthreads();
    }

    // ---------------- epilogue ----------------
    #pragma unroll
    for (int mf = 0; mf < 4; mf++) {
        #pragma unroll
        for (int half = 0; half < 2; half++) {
            int m = (int)bm + wm + mf * 16 + r + half * 8;
            size_t orow;
            bool ok = true;
            if (FINAL) {
                int bb = m >> 11, j = m & 2047;
                ok = j < VALID;
                orow = ((size_t)bb * S_ + j + (CHK_ - 1)) * 1024;
            } else {
                orow = (size_t)m * 1024;
            }
            if (!ok) continue;
            #pragma unroll
            for (int nf = 0; nf < 8; nf++) {
                int col = (int)bn + wn + nf * 8 + 2 * c;
                float v0 = acc[mf][nf][half * 2 + 0] + bias[col];
                float v1 = acc[mf][nf][half * 2 + 1] + bias[col + 1];
                if (FINAL) {
                    v0 += resid[orow + col];
                    v1 += resid[orow + col + 1];
                }
                float2 vv = make_float2(v0, v1);
                *(float2*)(out + orow + col) = vv;
            }
        }
    }
}

// ================= 3) attention per (b,c,h) =================
__global__ void __launch_bounds__(256) attn_kernel() {
    extern __shared__ float smf[];
    float* qs = smf;
    float* ks = smf + 64 * 68;
    float* sc = smf + 2 * 64 * 68;
    int blk = blockIdx.x;
    int hh  = blk & 15;
    int bc  = blk >> 4;
    const float* qp = g_q + (size_t)bc * 64 * 1024 + hh * 64;
    const float* kp = g_k + (size_t)bc * 256 * 1024 + hh * 64;
    const float* vp = g_v + (size_t)bc * 256 * 1024 + hh * 64;
    int t = threadIdx.x;

    #pragma unroll
    for (int r = 0; r < 16; r++) {
        int idx = t + r * 256;
        int i = idx >> 6, d = idx & 63;
        qs[i * 68 + d] = qp[(size_t)i * 1024 + d];
    }
    for (int jt = 0; jt < 4; jt++) {
        __syncthreads();
        #pragma unroll
        for (int r = 0; r < 16; r++) {
            int idx = t + r * 256;
            int j = idx >> 6, d = idx & 63;
            ks[j * 68 + d] = kp[(size_t)(jt * 64 + j) * 1024 + d];
        }
        __syncthreads();
        #pragma unroll
        for (int r = 0; r < 16; r++) {
            int idx = t + r * 256;
            int i = idx >> 6, j = idx & 63;
            float s = 0.f;
            #pragma unroll
            for (int kk = 0; kk < 16; kk++) {
                float4 qa = *(const float4*)&qs[i * 68 + kk * 4];
                float4 kb = *(const float4*)&ks[j * 68 + kk * 4];
                s += qa.x * kb.x + qa.y * kb.y + qa.z * kb.z + qa.w * kb.w;
            }
            sc[i * 256 + jt * 64 + j] = s * SCALE;
        }
    }
    __syncthreads();
    {
        int w = t >> 5, l = t & 31;
        for (int rr = 0; rr < 8; rr++) {
            float* row = sc + (w * 8 + rr) * 256;
            float m = -1e30f;
            float ev[8];
            #pragma unroll
            for (int cc = 0; cc < 8; cc++) m = fmaxf(m, row[l + cc * 32]);
            #pragma unroll
            for (int o = 16; o; o >>= 1) m = fmaxf(m, __shfl_xor_sync(0xffffffffu, m, o));
            float sum = 0.f;
            #pragma unroll
            for (int cc = 0; cc < 8; cc++) { ev[cc] = expf(row[l + cc * 32] - m); sum += ev[cc]; }
            #pragma unroll
            for (int o = 16; o; o >>= 1) sum += __shfl_xor_sync(0xffffffffu, sum, o);
            float inv = 1.f / sum;
            #pragma unroll
            for (int cc = 0; cc < 8; cc++) row[l + cc * 32] = ev[cc] * inv;
        }
    }
    float acc[4][4] = {};
    int tx = t & 15, ty = t >> 4;
    for (int jt = 0; jt < 4; jt++) {
        __syncthreads();
        #pragma unroll
        for (int r = 0; r < 16; r++) {
            int idx = t + r * 256;
            int j = idx >> 6, d = idx & 63;
            ks[j * 68 + d] = vp[(size_t)(jt * 64 + j) * 1024 + d];
        }
        __syncthreads();
        #pragma unroll 4
        for (int jj = 0; jj < 64; jj++) {
            float4 vv = *(const float4*)&ks[jj * 68 + tx * 4];
            float p[4];
            #pragma unroll
            for (int ii = 0; ii < 4; ii++) p[ii] = sc[(ty * 4 + ii) * 256 + jt * 64 + jj];
            #pragma unroll
            for (int ii = 0; ii < 4; ii++) {
                acc[ii][0] += p[ii] * vv.x;
                acc[ii][1] += p[ii] * vv.y;
                acc[ii][2] += p[ii] * vv.z;
                acc[ii][3] += p[ii] * vv.w;
            }
        }
    }
    float* op = g_ao + (size_t)bc * 64 * 1024 + hh * 64;
    #pragma unroll
    for (int ii = 0; ii < 4; ii++) {
        float4 v4 = make_float4(acc[ii][0], acc[ii][1], acc[ii][2], acc[ii][3]);
        *(float4*)(op + (size_t)(ty * 4 + ii) * 1024 + tx * 4) = v4;
    }
}

// ================= 4) rows 0..62: pure residual =================
__global__ void __launch_bounds__(256) head_copy(const float* __restrict__ h,
                                                 float* __restrict__ out) {
    int idx = blockIdx.x * 256 + threadIdx.x;
    int d = idx & 1023;
    int r = idx >> 10;
    int b = r / 63, tt = r % 63;
    size_t off = ((size_t)b * S_ + tt) * 1024 + d;
    out[off] = h[off];
}

// ================= launch =================
extern "C" void kernel_launch(void* const* d_in, const int* in_sizes, int n_in,
                              void* d_out, int out_size) {
    const float* h     = (const float*)d_in[0];
    const float* e     = (const float*)d_in[1];
    const float* Wq    = (const float*)d_in[2];
    const float* bq    = (const float*)d_in[3];
    const float* Wk    = (const float*)d_in[4];
    const float* bk    = (const float*)d_in[5];
    const float* Wv    = (const float*)d_in[6];
    const float* bv    = (const float*)d_in[7];
    const float* Wo    = (const float*)d_in[8];
    const float* bo    = (const float*)d_in[9];
    const float* gamma = (const float*)d_in[10];
    const float* beta  = (const float*)d_in[11];
    float* out = (float*)d_out;

    float *hb, *q, *k, *v, *ao;
    cudaGetSymbolAddress((void**)&hb, g_hb);
    cudaGetSymbolAddress((void**)&q,  g_q);
    cudaGetSymbolAddress((void**)&k,  g_k);
    cudaGetSymbolAddress((void**)&v,  g_v);
    cudaGetSymbolAddress((void**)&ao, g_ao);

    cudaFuncSetAttribute(gemm_tc<false>, cudaFuncAttributeMaxDynamicSharedMemorySize, GEMM_SMEM);
    cudaFuncSetAttribute(gemm_tc<true>,  cudaFuncAttributeMaxDynamicSharedMemorySize, GEMM_SMEM);

    head_copy<<<(B_ * 63 * 1024) / 256, 256>>>(h, out);
    ln_kernel<<<MQ, 256>>>(h, gamma, beta);

    gemm_tc<false><<<dim3(8, MQ  / 128), 128, GEMM_SMEM>>>(hb, Wq, bq, nullptr, q);
    gemm_tc<false><<<dim3(8, MKV / 128), 128, GEMM_SMEM>>>(e,  Wk, bk, nullptr, k);
    gemm_tc<false><<<dim3(8, MKV / 128), 128, GEMM_SMEM>>>(e,  Wv, bv, nullptr, v);

    int attn_smem = (2 * 64 * 68 + 64 * 256) * (int)sizeof(float);
    cudaFuncSetAttribute(attn_kernel, cudaFuncAttributeMaxDynamicSharedMemorySize, attn_smem);
    attn_kernel<<<B_ * C_ * H_, 256, attn_smem>>>();

    gemm_tc<true><<<dim3(8, MQ / 128), 128, GEMM_SMEM>>>(ao, Wo, bo, h, out);
}

// round 5
// speedup vs baseline: 2.6723x; 1.2010x over previous
#include <cuda_runtime.h>
#include <cstdint>

// ---------------- problem constants ----------------
constexpr int B_    = 4;
constexpr int S_    = 2048;
constexpr int D_    = 1024;
constexpr int C_    = 32;
constexpr int H_    = 16;
constexpr int CHK_  = 64;
constexpr int VALID = S_ - (CHK_ - 1);   // 1985
constexpr int MQ    = B_ * C_ * CHK_;    // 8192
constexpr int MKV   = B_ * C_ * 256;     // 32768
constexpr float SCALE = 0.125f;
constexpr float EPS_  = 1e-5f;

// ---------------- scratch ----------------
__device__ float g_hb[(size_t)MQ  * D_];
__device__ float g_q [(size_t)MQ  * D_];
__device__ float g_k [(size_t)MKV * D_];
__device__ float g_v [(size_t)MKV * D_];
__device__ float g_ao[(size_t)MQ  * D_];
__device__ float g_er[(size_t)MKV * D_];          // tf32-rounded e
__device__ float g_wr[4 * (size_t)D_ * D_];       // tf32-rounded Wq,Wk,Wv,Wo

// ---------------- PTX helpers ----------------
__device__ __forceinline__ uint32_t smem_u32(const void* p) {
    uint32_t a;
    asm("{ .reg .u64 t; cvta.to.shared.u64 t, %1; cvt.u32.u64 %0, t; }" : "=r"(a) : "l"(p));
    return a;
}
__device__ __forceinline__ void cp16(uint32_t dst, const void* src) {
    asm volatile("cp.async.cg.shared.global [%0], [%1], 16;" :: "r"(dst), "l"(src) : "memory");
}
#define CP_COMMIT() asm volatile("cp.async.commit_group;" ::: "memory")

__device__ __forceinline__ float f2tf_f(float x) {
    uint32_t r;
    asm("cvt.rna.tf32.f32 %0, %1;" : "=r"(r) : "f"(x));
    return __uint_as_float(r);
}
__device__ __forceinline__ void mma8(float* d, const uint32_t* a, const uint32_t* b) {
    asm volatile("mma.sync.aligned.m16n8k8.row.col.f32.tf32.tf32.f32 "
        "{%0,%1,%2,%3}, {%4,%5,%6,%7}, {%8,%9}, {%0,%1,%2,%3};"
        : "+f"(d[0]), "+f"(d[1]), "+f"(d[2]), "+f"(d[3])
        : "r"(a[0]), "r"(a[1]), "r"(a[2]), "r"(a[3]), "r"(b[0]), "r"(b[1]));
}

// ---------------- 0) tf32 rounding pass ----------------
__global__ void __launch_bounds__(256) round_tf32(const float* __restrict__ src,
                                                  float* __restrict__ dst, int n4) {
    int i = blockIdx.x * 256 + threadIdx.x;
    if (i < n4) {
        float4 v = ((const float4*)src)[i];
        v.x = f2tf_f(v.x); v.y = f2tf_f(v.y);
        v.z = f2tf_f(v.z); v.w = f2tf_f(v.w);
        ((float4*)dst)[i] = v;
    }
}

// ---------------- 1) LayerNorm + shift (writes tf32-rounded) ----------------
__global__ void __launch_bounds__(256) ln_kernel(const float* __restrict__ h,
                                                 const float* __restrict__ gamma,
                                                 const float* __restrict__ beta) {
    int row = blockIdx.x;
    int b = row >> 11, j = row & 2047;
    float* dst = g_hb + (size_t)row * D_;
    int t = threadIdx.x;
    if (j >= VALID) {
        for (int i = t; i < D_; i += 256) dst[i] = 0.f;
        return;
    }
    const float* src = h + ((size_t)b * S_ + (j + CHK_ - 1)) * D_;
    float x[4];
    float s = 0.f, ss = 0.f;
    #pragma unroll
    for (int r = 0; r < 4; r++) {
        float v = src[t + r * 256];
        x[r] = v; s += v; ss += v * v;
    }
    #pragma unroll
    for (int o = 16; o; o >>= 1) {
        s  += __shfl_down_sync(0xffffffffu, s,  o);
        ss += __shfl_down_sync(0xffffffffu, ss, o);
    }
    __shared__ float rs[8], rss[8];
    int w = t >> 5, l = t & 31;
    if (l == 0) { rs[w] = s; rss[w] = ss; }
    __syncthreads();
    float S1 = 0.f, S2 = 0.f;
    #pragma unroll
    for (int i = 0; i < 8; i++) { S1 += rs[i]; S2 += rss[i]; }
    float mu  = S1 * (1.f / D_);
    float var = S2 * (1.f / D_) - mu * mu;
    float inv = rsqrtf(var + EPS_);
    #pragma unroll
    for (int r = 0; r < 4; r++) {
        int c = t + r * 256;
        dst[c] = f2tf_f((x[r] - mu) * inv * gamma[c] + beta[c]);
    }
}

// ================= 2) tf32 mma.sync GEMM =================
// CTA tile 128x128, BK=32, 8 warps (warp tile 32x64), 3-stage cp.async pipe.
// Operands pre-rounded to tf32 in gmem -> NO cvt in hot loop.
// A_s[m][36]: frag bank = 4r+c (bijective). B_s[k][136]: bank = 8c+r (bijective).
constexpr int AS_STRIDE = 36;
constexpr int BS_STRIDE = 136;
constexpr int A_STAGE_W = 128 * AS_STRIDE;        // 4608
constexpr int B_STAGE_W = 32 * BS_STRIDE;         // 4352
constexpr int STAGE_W   = A_STAGE_W + B_STAGE_W;  // 8960
constexpr int GEMM_SMEM = 3 * STAGE_W * 4;        // 107520 B

template <bool FINAL>
__global__ void __launch_bounds__(256, 2) gemm_tc(const float* __restrict__ A,
                                                  const float* __restrict__ W,
                                                  const float* __restrict__ bias,
                                                  const float* __restrict__ resid,
                                                  float* __restrict__ out) {
    extern __shared__ float sm[];
    const uint32_t smb = smem_u32(sm);

    const int t    = threadIdx.x;
    const int lane = t & 31;
    const int w    = t >> 5;             // 0..7
    const int wm   = (w >> 1) * 32;      // 0,32,64,96
    const int wn   = (w & 1) * 64;       // 0,64
    const int r    = lane >> 2;          // 0..7
    const int c    = lane & 3;           // 0..3

    const size_t bm = (size_t)blockIdx.y * 128;
    const size_t bn = (size_t)blockIdx.x * 128;

    // loader indices (256 threads)
    const int arow = t >> 3;             // 0..31
    const int ac8  = t & 7;
    const int bkk  = t >> 3;             // 0..31 (k row)
    const int bcg  = t & 7;              // n float4 group base

    const float* Ag = A + (bm + arow) * 1024 + ac8 * 4;
    const float* Wg = W + (size_t)bkk * 1024 + bn + bcg * 4;

    auto load_stage = [&](int s, int buf) {
        uint32_t abase = smb + (uint32_t)buf * STAGE_W * 4;
        uint32_t bbase = abase + A_STAGE_W * 4;
        const float* Asrc = Ag + s * 32;
        #pragma unroll
        for (int p = 0; p < 4; p++) {
            int row = arow + p * 32;
            cp16(abase + (uint32_t)(row * AS_STRIDE + ac8 * 4) * 4, Asrc + (size_t)p * 32 * 1024);
        }
        const float* Bsrc = Wg + (size_t)s * 32 * 1024;
        #pragma unroll
        for (int i = 0; i < 4; i++) {
            int n4 = bcg + i * 8;
            cp16(bbase + (uint32_t)(bkk * BS_STRIDE + n4 * 4) * 4, Bsrc + (size_t)i * 32);
        }
    };

    float acc[2][8][4];
    #pragma unroll
    for (int i = 0; i < 2; i++)
        #pragma unroll
        for (int j = 0; j < 8; j++)
            #pragma unroll
            for (int q = 0; q < 4; q++) acc[i][j][q] = 0.f;

    load_stage(0, 0); CP_COMMIT();
    load_stage(1, 1); CP_COMMIT();

    for (int s = 0; s < 32; s++) {
        if (s >= 30) { asm volatile("cp.async.wait_group 0;" ::: "memory"); }
        else         { asm volatile("cp.async.wait_group 1;" ::: "memory"); }
        __syncthreads();
        if (s + 2 < 32) { load_stage(s + 2, (s + 2) % 3); CP_COMMIT(); }

        const uint32_t* As = (const uint32_t*)(sm + (s % 3) * STAGE_W);
        const uint32_t* Bs = As + A_STAGE_W;
        #pragma unroll
        for (int ks = 0; ks < 4; ks++) {
            const int k8 = ks * 8;
            uint32_t a[2][4], b[8][2];
            #pragma unroll
            for (int mf = 0; mf < 2; mf++) {
                int m0 = wm + mf * 16 + r;
                a[mf][0] = As[m0 * AS_STRIDE + k8 + c];
                a[mf][1] = As[(m0 + 8) * AS_STRIDE + k8 + c];
                a[mf][2] = As[m0 * AS_STRIDE + k8 + c + 4];
                a[mf][3] = As[(m0 + 8) * AS_STRIDE + k8 + c + 4];
            }
            #pragma unroll
            for (int nf = 0; nf < 8; nf++) {
                int n0 = wn + nf * 8 + r;
                b[nf][0] = Bs[(k8 + c) * BS_STRIDE + n0];
                b[nf][1] = Bs[(k8 + c + 4) * BS_STRIDE + n0];
            }
            #pragma unroll
            for (int mf = 0; mf < 2; mf++)
                #pragma unroll
                for (int nf = 0; nf < 8; nf++)
                    mma8(acc[mf][nf], a[mf], b[nf]);
        }
        __syncthreads();
    }

    // ---------------- epilogue ----------------
    #pragma unroll
    for (int mf = 0; mf < 2; mf++) {
        #pragma unroll
        for (int half = 0; half < 2; half++) {
            int m = (int)bm + wm + mf * 16 + r + half * 8;
            size_t orow;
            bool ok = true;
            if (FINAL) {
                int bb = m >> 11, j = m & 2047;
                ok = j < VALID;
                orow = ((size_t)bb * S_ + j + (CHK_ - 1)) * 1024;
            } else {
                orow = (size_t)m * 1024;
            }
            if (!ok) continue;
            #pragma unroll
            for (int nf = 0; nf < 8; nf++) {
                int col = (int)bn + wn + nf * 8 + 2 * c;
                float v0 = acc[mf][nf][half * 2 + 0] + bias[col];
                float v1 = acc[mf][nf][half * 2 + 1] + bias[col + 1];
                if (FINAL) {
                    v0 += resid[orow + col];
                    v1 += resid[orow + col + 1];
                }
                float2 vv = make_float2(v0, v1);
                *(float2*)(out + orow + col) = vv;
            }
        }
    }
}

// ================= 3) attention per (b,c,h) =================
__global__ void __launch_bounds__(256) attn_kernel() {
    extern __shared__ float smf[];
    float* qs = smf;
    float* ks = smf + 64 * 68;
    float* sc = smf + 2 * 64 * 68;
    int blk = blockIdx.x;
    int hh  = blk & 15;
    int bc  = blk >> 4;
    const float* qp = g_q + (size_t)bc * 64 * 1024 + hh * 64;
    const float* kp = g_k + (size_t)bc * 256 * 1024 + hh * 64;
    const float* vp = g_v + (size_t)bc * 256 * 1024 + hh * 64;
    int t = threadIdx.x;

    #pragma unroll
    for (int r = 0; r < 16; r++) {
        int idx = t + r * 256;
        int i = idx >> 6, d = idx & 63;
        qs[i * 68 + d] = qp[(size_t)i * 1024 + d];
    }
    for (int jt = 0; jt < 4; jt++) {
        __syncthreads();
        #pragma unroll
        for (int r = 0; r < 16; r++) {
            int idx = t + r * 256;
            int j = idx >> 6, d = idx & 63;
            ks[j * 68 + d] = kp[(size_t)(jt * 64 + j) * 1024 + d];
        }
        __syncthreads();
        #pragma unroll
        for (int r = 0; r < 16; r++) {
            int idx = t + r * 256;
            int i = idx >> 6, j = idx & 63;
            float s = 0.f;
            #pragma unroll
            for (int kk = 0; kk < 16; kk++) {
                float4 qa = *(const float4*)&qs[i * 68 + kk * 4];
                float4 kb = *(const float4*)&ks[j * 68 + kk * 4];
                s += qa.x * kb.x + qa.y * kb.y + qa.z * kb.z + qa.w * kb.w;
            }
            sc[i * 256 + jt * 64 + j] = s * SCALE;
        }
    }
    __syncthreads();
    {
        int w = t >> 5, l = t & 31;
        for (int rr = 0; rr < 8; rr++) {
            float* row = sc + (w * 8 + rr) * 256;
            float m = -1e30f;
            float ev[8];
            #pragma unroll
            for (int cc = 0; cc < 8; cc++) m = fmaxf(m, row[l + cc * 32]);
            #pragma unroll
            for (int o = 16; o; o >>= 1) m = fmaxf(m, __shfl_xor_sync(0xffffffffu, m, o));
            float sum = 0.f;
            #pragma unroll
            for (int cc = 0; cc < 8; cc++) { ev[cc] = expf(row[l + cc * 32] - m); sum += ev[cc]; }
            #pragma unroll
            for (int o = 16; o; o >>= 1) sum += __shfl_xor_sync(0xffffffffu, sum, o);
            float inv = 1.f / sum;
            #pragma unroll
            for (int cc = 0; cc < 8; cc++) row[l + cc * 32] = ev[cc] * inv;
        }
    }
    float acc[4][4] = {};
    int tx = t & 15, ty = t >> 4;
    for (int jt = 0; jt < 4; jt++) {
        __syncthreads();
        #pragma unroll
        for (int r = 0; r < 16; r++) {
            int idx = t + r * 256;
            int j = idx >> 6, d = idx & 63;
            ks[j * 68 + d] = vp[(size_t)(jt * 64 + j) * 1024 + d];
        }
        __syncthreads();
        #pragma unroll 4
        for (int jj = 0; jj < 64; jj++) {
            float4 vv = *(const float4*)&ks[jj * 68 + tx * 4];
            float p[4];
            #pragma unroll
            for (int ii = 0; ii < 4; ii++) p[ii] = sc[(ty * 4 + ii) * 256 + jt * 64 + jj];
            #pragma unroll
            for (int ii = 0; ii < 4; ii++) {
                acc[ii][0] += p[ii] * vv.x;
                acc[ii][1] += p[ii] * vv.y;
                acc[ii][2] += p[ii] * vv.z;
                acc[ii][3] += p[ii] * vv.w;
            }
        }
    }
    float* op = g_ao + (size_t)bc * 64 * 1024 + hh * 64;
    #pragma unroll
    for (int ii = 0; ii < 4; ii++) {
        // round to tf32 so the final GEMM's A operand needs no cvt
        float4 v4 = make_float4(f2tf_f(acc[ii][0]), f2tf_f(acc[ii][1]),
                                f2tf_f(acc[ii][2]), f2tf_f(acc[ii][3]));
        *(float4*)(op + (size_t)(ty * 4 + ii) * 1024 + tx * 4) = v4;
    }
}

// ================= 4) rows 0..62: pure residual =================
__global__ void __launch_bounds__(256) head_copy(const float* __restrict__ h,
                                                 float* __restrict__ out) {
    int idx = blockIdx.x * 256 + threadIdx.x;
    int d = idx & 1023;
    int r = idx >> 10;
    int b = r / 63, tt = r % 63;
    size_t off = ((size_t)b * S_ + tt) * 1024 + d;
    out[off] = h[off];
}

// ================= launch =================
extern "C" void kernel_launch(void* const* d_in, const int* in_sizes, int n_in,
                              void* d_out, int out_size) {
    const float* h     = (const float*)d_in[0];
    const float* e     = (const float*)d_in[1];
    const float* Wq    = (const float*)d_in[2];
    const float* bq    = (const float*)d_in[3];
    const float* Wk    = (const float*)d_in[4];
    const float* bk    = (const float*)d_in[5];
    const float* Wv    = (const float*)d_in[6];
    const float* bv    = (const float*)d_in[7];
    const float* Wo    = (const float*)d_in[8];
    const float* bo    = (const float*)d_in[9];
    const float* gamma = (const float*)d_in[10];
    const float* beta  = (const float*)d_in[11];
    float* out = (float*)d_out;

    float *hb, *q, *k, *v, *ao, *er, *wr;
    cudaGetSymbolAddress((void**)&hb, g_hb);
    cudaGetSymbolAddress((void**)&q,  g_q);
    cudaGetSymbolAddress((void**)&k,  g_k);
    cudaGetSymbolAddress((void**)&v,  g_v);
    cudaGetSymbolAddress((void**)&ao, g_ao);
    cudaGetSymbolAddress((void**)&er, g_er);
    cudaGetSymbolAddress((void**)&wr, g_wr);
    const size_t WSZ = (size_t)D_ * D_;

    cudaFuncSetAttribute(gemm_tc<false>, cudaFuncAttributeMaxDynamicSharedMemorySize, GEMM_SMEM);
    cudaFuncSetAttribute(gemm_tc<true>,  cudaFuncAttributeMaxDynamicSharedMemorySize, GEMM_SMEM);

    head_copy<<<(B_ * 63 * 1024) / 256, 256>>>(h, out);
    ln_kernel<<<MQ, 256>>>(h, gamma, beta);

    round_tf32<<<(int)(MKV * (size_t)D_ / 4 / 256), 256>>>(e, er, (int)(MKV * (size_t)D_ / 4));
    round_tf32<<<(int)(WSZ / 4 / 256), 256>>>(Wq, wr + 0 * WSZ, (int)(WSZ / 4));
    round_tf32<<<(int)(WSZ / 4 / 256), 256>>>(Wk, wr + 1 * WSZ, (int)(WSZ / 4));
    round_tf32<<<(int)(WSZ / 4 / 256), 256>>>(Wv, wr + 2 * WSZ, (int)(WSZ / 4));
    round_tf32<<<(int)(WSZ / 4 / 256), 256>>>(Wo, wr + 3 * WSZ, (int)(WSZ / 4));

    gemm_tc<false><<<dim3(8, MQ  / 128), 256, GEMM_SMEM>>>(hb, wr + 0 * WSZ, bq, nullptr, q);
    gemm_tc<false><<<dim3(8, MKV / 128), 256, GEMM_SMEM>>>(er, wr + 1 * WSZ, bk, nullptr, k);
    gemm_tc<false><<<dim3(8, MKV / 128), 256, GEMM_SMEM>>>(er, wr + 2 * WSZ, bv, nullptr, v);

    int attn_smem = (2 * 64 * 68 + 64 * 256) * (int)sizeof(float);
    cudaFuncSetAttribute(attn_kernel, cudaFuncAttributeMaxDynamicSharedMemorySize, attn_smem);
    attn_kernel<<<B_ * C_ * H_, 256, attn_smem>>>();

    gemm_tc<true><<<dim3(8, MQ / 128), 256, GEMM_SMEM>>>(ao, wr + 3 * WSZ, bo, h, out);
}